// round 6
// baseline (speedup 1.0000x reference)
#include <cuda_runtime.h>
#include <cuda_bf16.h>
#include <math_constants.h>

// Problem shape (fixed by the reference)
#define L_DIM 1024
#define B_DIM 64
#define H_DIM 1024
#define N_ROWS (L_DIM * B_DIM)          // 65536 flat rows, b-major: row = b*1024 + l

#define G_CTAS 296                      // 148 SMs x 2 CTAs -> perfectly balanced
#define WARPS_PER_BLOCK 8
#define HV 8                            // float4 vectors per thread (H/128)
#define MAXC 8                          // max contributing slots per b (<= 6 actual)

// Scratch: one partial per (cta, segment). 592 slots x 4KB ~= 2.4 MB.
__device__ float g_ctx[2 * G_CTAS * H_DIM];
__device__ float g_m[2 * G_CTAS];
__device__ float g_d[2 * G_CTAS];
__device__ int   g_tag[2 * G_CTAS];     // b+1 of the partial in this slot (0 = never used)
__device__ int   g_rows[B_DIM];         // rows accumulated per b; reset by combiner

// ---------------------------------------------------------------------------
// One balanced fused kernel. grid = 296, block = 256 (8 warps), occ 2.
// CTA i owns flat rows [i*N/G, (i+1)*N/G) -> 221..222 rows, <= 2 b-segments.
// ---------------------------------------------------------------------------
__global__ __launch_bounds__(256, 2)
void attn_fused(const float* __restrict__ enc,   // [L, B, H]
                const float* __restrict__ dec,   // [1, B, H]
                float* __restrict__ out)         // [B, H]
{
    const int cta  = blockIdx.x;
    const int warp = threadIdx.x >> 5;
    const int lane = threadIdx.x & 31;

    __shared__ float s_acc[WARPS_PER_BLOCK][H_DIM];   // 32 KB
    __shared__ float s_m[WARPS_PER_BLOCK];
    __shared__ float s_d[WARPS_PER_BLOCK];
    __shared__ float s_scale[WARPS_PER_BLOCK];
    __shared__ int   s_is_last;

    const int r0 = (cta * N_ROWS) / G_CTAS;
    const int r1 = ((cta + 1) * N_ROWS) / G_CTAS;
    const int b0   = r0 >> 10;
    const int bend = (r1 - 1) >> 10;
    const int nseg = (bend > b0) ? 2 : 1;

    for (int seg = 0; seg < nseg; seg++) {
        const int b  = b0 + seg;
        const int s0 = max(r0, b << 10);
        const int s1 = min(r1, (b + 1) << 10);
        const int seg_rows = s1 - s0;

        // Stage decoder row for this b in registers.
        const float4* dec4 = reinterpret_cast<const float4*>(dec + (size_t)b * H_DIM);
        float4 dv[HV];
#pragma unroll
        for (int k = 0; k < HV; k++) dv[k] = dec4[k * 32 + lane];

        float4 acc[HV];
#pragma unroll
        for (int k = 0; k < HV; k++) acc[k] = make_float4(0.f, 0.f, 0.f, 0.f);
        float m = -CUDART_INF_F;
        float d = 0.f;

        for (int r = s0 + warp; r < s1; r += WARPS_PER_BLOCK) {
            const int l = r & 1023;
            const float4* e4 =
                reinterpret_cast<const float4*>(enc + ((size_t)l * B_DIM + b) * H_DIM);
            float4 ev[HV];
#pragma unroll
            for (int k = 0; k < HV; k++) ev[k] = __ldcs(&e4[k * 32 + lane]);  // MLP=8

            float sc = 0.f;
#pragma unroll
            for (int k = 0; k < HV; k++) {
                sc = fmaf(ev[k].x, dv[k].x, sc);
                sc = fmaf(ev[k].y, dv[k].y, sc);
                sc = fmaf(ev[k].z, dv[k].z, sc);
                sc = fmaf(ev[k].w, dv[k].w, sc);
            }
#pragma unroll
            for (int off = 16; off > 0; off >>= 1)
                sc += __shfl_xor_sync(0xffffffffu, sc, off);

            if (sc > m) {
                // Rare path: new running max; w = 1 exactly.
                const float alpha = __expf(m - sc);   // 0 on first iteration
                d = fmaf(d, alpha, 1.0f);
                m = sc;
#pragma unroll
                for (int k = 0; k < HV; k++) {
                    acc[k].x = fmaf(acc[k].x, alpha, ev[k].x);
                    acc[k].y = fmaf(acc[k].y, alpha, ev[k].y);
                    acc[k].z = fmaf(acc[k].z, alpha, ev[k].z);
                    acc[k].w = fmaf(acc[k].w, alpha, ev[k].w);
                }
            } else {
                const float w = __expf(sc - m);
                d += w;
#pragma unroll
                for (int k = 0; k < HV; k++) {
                    acc[k].x = fmaf(w, ev[k].x, acc[k].x);
                    acc[k].y = fmaf(w, ev[k].y, acc[k].y);
                    acc[k].z = fmaf(w, ev[k].z, acc[k].z);
                    acc[k].w = fmaf(w, ev[k].w, acc[k].w);
                }
            }
        }

        // ---- in-block flash combine of the 8 warp partials ----
        __syncthreads();   // protect s_acc reuse across segments
#pragma unroll
        for (int k = 0; k < HV; k++)
            *reinterpret_cast<float4*>(&s_acc[warp][k * 128 + lane * 4]) = acc[k];
        if (lane == 0) { s_m[warp] = m; s_d[warp] = d; }
        __syncthreads();

        const int slot = 2 * cta + seg;
        if (threadIdx.x == 0) {
            float M = -CUDART_INF_F;
#pragma unroll
            for (int w = 0; w < WARPS_PER_BLOCK; w++)
                if (s_d[w] > 0.f) M = fmaxf(M, s_m[w]);
            float D = 0.f;
#pragma unroll
            for (int w = 0; w < WARPS_PER_BLOCK; w++) {
                float sc = (s_d[w] > 0.f) ? __expf(s_m[w] - M) : 0.f;
                s_scale[w] = sc;
                D += s_d[w] * sc;
            }
            g_m[slot] = M;
            g_d[slot] = D;
            g_tag[slot] = b + 1;
        }
        __syncthreads();

        {
            const int h = threadIdx.x * 4;
            float4 sum = make_float4(0.f, 0.f, 0.f, 0.f);
#pragma unroll
            for (int w = 0; w < WARPS_PER_BLOCK; w++) {
                float sc = s_scale[w];
                float4 v = *reinterpret_cast<const float4*>(&s_acc[w][h]);
                sum.x = fmaf(sc, v.x, sum.x);
                sum.y = fmaf(sc, v.y, sum.y);
                sum.z = fmaf(sc, v.z, sum.z);
                sum.w = fmaf(sc, v.w, sum.w);
            }
            *reinterpret_cast<float4*>(&g_ctx[(size_t)slot * H_DIM + h]) = sum;
        }

        // ---- arrival: count rows; the CTA reaching 1024 combines b ----
        __threadfence();
        if (threadIdx.x == 0) {
            int old = atomicAdd(&g_rows[b], seg_rows);
            s_is_last = (old + seg_rows == L_DIM) ? 1 : 0;
        }
        __syncthreads();
        if (!s_is_last) continue;

        __threadfence();   // order reads of peers' partials after the atomic

        // Candidate contributor CTAs form a contiguous window around b.
        int ilo = max(0, ((b << 10) * G_CTAS) / N_ROWS - 1);
        int ihi = min(G_CTAS - 1, (((b + 1) << 10) * G_CTAS) / N_ROWS + 1);

        int   slots[MAXC];
        int   nc = 0;
        for (int i = ilo; i <= ihi && nc < MAXC; i++) {
#pragma unroll
            for (int sg = 0; sg < 2; sg++) {
                int sl = 2 * i + sg;
                if (g_tag[sl] == b + 1 && nc < MAXC) slots[nc++] = sl;
            }
        }

        float M = -CUDART_INF_F;
        for (int p = 0; p < nc; p++) M = fmaxf(M, g_m[slots[p]]);
        float D = 0.f;
        float scl[MAXC];
        for (int p = 0; p < nc; p++) {
            scl[p] = __expf(g_m[slots[p]] - M);
            D += g_d[slots[p]] * scl[p];
        }
        const float invD = 1.f / D;

        {
            const int h = threadIdx.x * 4;
            float4 sum = make_float4(0.f, 0.f, 0.f, 0.f);
            for (int p = 0; p < nc; p++) {
                const float sc = scl[p] * invD;
                float4 v = *reinterpret_cast<const float4*>(
                    &g_ctx[(size_t)slots[p] * H_DIM + h]);
                sum.x = fmaf(sc, v.x, sum.x);
                sum.y = fmaf(sc, v.y, sum.y);
                sum.z = fmaf(sc, v.z, sum.z);
                sum.w = fmaf(sc, v.w, sum.w);
            }
            *reinterpret_cast<float4*>(&out[(size_t)b * H_DIM + h]) = sum;
        }

        if (threadIdx.x == 0) g_rows[b] = 0;   // reset for next graph replay
    }
}

// ---------------------------------------------------------------------------
extern "C" void kernel_launch(void* const* d_in, const int* in_sizes, int n_in,
                              void* d_out, int out_size)
{
    const float* enc = (const float*)d_in[0];   // [1024, 64, 1024]
    const float* dec = (const float*)d_in[1];   // [1, 64, 1024]
    float* out = (float*)d_out;                 // [64, 1024]

    attn_fused<<<G_CTAS, 256>>>(enc, dec, out);
}